// round 16
// baseline (speedup 1.0000x reference)
#include <cuda_runtime.h>
#include <cuda_fp16.h>
#include <math.h>
#include <stdint.h>

#define NN   50000
#define EE   800000
#define EQ   (EE / 4)
#define D    128
#define DOUT 10
#define GG   128
#define CAP  96        // bucket capacity (P(deg>=96) ~ 1e-45 for Poisson(16))

#define NPAD (((NN + 127) / 128) * 128)
#define NT   ((NN + 127) / 128)    // 391 tiles
#define NH   25088                 // node split (=196 tiles)
#define TH   (NH / 128)            // 196

// ---------------- device scratch (3-buffer rotation) ----------------
__device__ __half g_h0[(size_t)NPAD * D];
__device__ __half g_h1[(size_t)NPAD * D];
__device__ __half g_h2[(size_t)NPAD * D];
__device__ __half g_Wt[3][D * D];
__device__ int    g_deg[NN];
__device__ float  g_dinv[NN];
__device__ int    g_colsrc[(size_t)NN * CAP];
__device__ float  g_psum[GG * D];
__device__ int    g_pcnt[GG];

// ---------------- single-pass bucket CSR ----------------
__global__ void k_fill(const int* __restrict__ ei) {
    int t = blockIdx.x * blockDim.x + threadIdx.x;
    if (t >= EQ) return;
    const int* dsts = ei + EE;
    int d0 = dsts[t];
    int d1 = dsts[t + EQ];
    int d2 = dsts[t + 2 * EQ];
    int d3 = dsts[t + 3 * EQ];
    int s0 = ei[t];
    int s1 = ei[t + EQ];
    int s2 = ei[t + 2 * EQ];
    int s3 = ei[t + 3 * EQ];
    int p0 = atomicAdd(&g_deg[d0], 1);
    int p1 = atomicAdd(&g_deg[d1], 1);
    int p2 = atomicAdd(&g_deg[d2], 1);
    int p3 = atomicAdd(&g_deg[d3], 1);
    if (p0 < CAP) g_colsrc[(size_t)d0 * CAP + p0] = s0;
    if (p1 < CAP) g_colsrc[(size_t)d1 * CAP + p1] = s1;
    if (p2 < CAP) g_colsrc[(size_t)d2 * CAP + p2] = s2;
    if (p3 < CAP) g_colsrc[(size_t)d3 * CAP + p3] = s3;
}

__global__ void k_dinv() {
    int i = blockIdx.x * blockDim.x + threadIdx.x;
    if (i < NN) g_dinv[i] = rsqrtf((float)(g_deg[i] + 1));
}

// ---------------- weight prep (+ pool buffer zeroing) ----------------
__global__ void k_wprep(const float* __restrict__ W1, const float* __restrict__ W2,
                        const float* __restrict__ W3) {
    int idx = blockIdx.x * blockDim.x + threadIdx.x;
    if (idx < GG * D) g_psum[idx] = 0.0f;
    if (idx < GG) g_pcnt[idx] = 0;
    if (idx >= 3 * D * D) return;
    int l = idx / (D * D);
    int j = idx - l * (D * D);
    int k = j >> 7, n = j & 127;
    const float* W = (l == 0) ? W1 : (l == 1) ? W2 : W3;
    g_Wt[l][n * D + k] = __float2half_rn(W[j]);
}

// ---------------- x -> fp16 stream convert (into g_h2) ----------------
__global__ void k_xconv(const float* __restrict__ x) {
    int idx = blockIdx.x * blockDim.x + threadIdx.x;
    if (idx >= NN * D / 4) return;
    float4 v = ((const float4*)x)[idx];
    __half2 a = __floats2half2_rn(v.x, v.y);
    __half2 b = __floats2half2_rn(v.z, v.w);
    uint2 u;
    u.x = *(uint32_t*)&a;
    u.y = *(uint32_t*)&b;
    ((uint2*)g_h2)[idx] = u;
}

// ---------------- fp16 tensor-core GEMM (tile-range, M=128, 2 CTA/SM) --------
#define SMSH 136
#define GEMM_SMEM (2 * 128 * SMSH * sizeof(__half))
#define GGRID 296

#define MMA_F16(cc, a0, a1, a2, a3, b0, b1)                               \
    asm volatile("mma.sync.aligned.m16n8k16.row.col.f32.f16.f16.f32 "     \
                 "{%0,%1,%2,%3}, {%4,%5,%6,%7}, {%8,%9}, {%0,%1,%2,%3};"  \
                 : "+f"(cc[0]), "+f"(cc[1]), "+f"(cc[2]), "+f"(cc[3])     \
                 : "r"(a0), "r"(a1), "r"(a2), "r"(a3), "r"(b0), "r"(b1))

template <bool SCALE>
__global__ void __launch_bounds__(256, 2)
k_gemm_h(const __half* __restrict__ A, int wsel, __half* __restrict__ C,
         int tile0, int tile1) {
    extern __shared__ __half smh[];
    __half* As = smh;
    __half* Wt = smh + 128 * SMSH;
    const int t = threadIdx.x;

    {
        const uint4* src = (const uint4*)g_Wt[wsel];
        for (int j = t; j < (D * D) / 8; j += 256) {
            int n = j >> 4;
            int c8 = (j & 15) * 8;
            *(uint4*)(Wt + n * SMSH + c8) = src[j];
        }
    }

    const int w    = t >> 5;
    const int lane = t & 31;
    const int wm   = w & 3;
    const int wn   = w >> 2;
    const int quad = lane >> 2;
    const int rem  = lane & 3;
    const __half* Ab = As + (wm * 32 + quad) * SMSH + 2 * rem;
    const __half* Bb = Wt + (wn * 64 + quad) * SMSH + 2 * rem;

    for (int tile = tile0 + blockIdx.x; tile < tile1; tile += gridDim.x) {
        const int row0 = tile * 128;
        __syncthreads();

        // stage A (fp16, padded buffers -> no guard)
        for (int j = t; j < (128 * D) / 8; j += 256) {
            int r = j >> 4;
            int c8 = (j & 15) * 8;
            uint4 u = *(const uint4*)(A + (size_t)(row0 + r) * D + c8);
            *(uint4*)(As + r * SMSH + c8) = u;
        }
        __syncthreads();

        float acc[2][8][4];
        #pragma unroll
        for (int m = 0; m < 2; m++)
            #pragma unroll
            for (int j = 0; j < 8; j++)
                #pragma unroll
                for (int r = 0; r < 4; r++) acc[m][j][r] = 0.f;

        #pragma unroll
        for (int ks = 0; ks < 8; ks++) {
            const int k0 = ks * 16;
            uint32_t a[2][4];
            #pragma unroll
            for (int m = 0; m < 2; m++) {
                const __half* p = Ab + m * 16 * SMSH + k0;
                a[m][0] = *(const uint32_t*)(p);
                a[m][1] = *(const uint32_t*)(p + 8 * SMSH);
                a[m][2] = *(const uint32_t*)(p + 8);
                a[m][3] = *(const uint32_t*)(p + 8 * SMSH + 8);
            }
            #pragma unroll
            for (int j = 0; j < 8; j++) {
                const __half* q = Bb + j * 8 * SMSH + k0;
                uint32_t b0 = *(const uint32_t*)(q);
                uint32_t b1 = *(const uint32_t*)(q + 8);
                MMA_F16(acc[0][j], a[0][0], a[0][1], a[0][2], a[0][3], b0, b1);
                MMA_F16(acc[1][j], a[1][0], a[1][1], a[1][2], a[1][3], b0, b1);
            }
        }

        #pragma unroll
        for (int m = 0; m < 2; m++) {
            int r = row0 + wm * 32 + m * 16 + quad;
            float di0 = 1.f, di1 = 1.f;
            if (SCALE) {
                di0 = (r < NN)     ? g_dinv[r]     : 0.f;
                di1 = (r + 8 < NN) ? g_dinv[r + 8] : 0.f;
            }
            #pragma unroll
            for (int j = 0; j < 8; j++) {
                int cb = wn * 64 + j * 8 + rem * 2;
                if (r < NN) {
                    __half2 h = __floats2half2_rn(acc[m][j][0] * di0, acc[m][j][1] * di0);
                    *(uint32_t*)(C + (size_t)r * D + cb) = *(uint32_t*)&h;
                }
                if (r + 8 < NN) {
                    __half2 h = __floats2half2_rn(acc[m][j][2] * di1, acc[m][j][3] * di1);
                    *(uint32_t*)(C + (size_t)(r + 8) * D + cb) = *(uint32_t*)&h;
                }
            }
        }
    }
}

// ---------------- 16-lane-per-row aggregation, MLP-8 + int4 index loads ------
__device__ __forceinline__ void addu4(const uint4& u, float* a) {
    const __half2* h = (const __half2*)&u;
    #pragma unroll
    for (int q = 0; q < 4; q++) {
        float2 f = __half22float2(h[q]);
        a[2 * q + 0] += f.x;
        a[2 * q + 1] += f.y;
    }
}

__device__ __forceinline__ void addu4_w(const uint4& u, float ds, float* a) {
    const __half2* h = (const __half2*)&u;
    #pragma unroll
    for (int q = 0; q < 4; q++) {
        float2 f = __half22float2(h[q]);
        a[2 * q + 0] += f.x * ds;
        a[2 * q + 1] += f.y * ds;
    }
}

__device__ __forceinline__ uint4 ldrow(const __half* __restrict__ H, int s, int sl) {
    return *(const uint4*)(H + (size_t)s * D + sl * 8);
}

// rows pre-scaled by dinv[s] (layers 2,3)
__device__ __forceinline__ void gather16(const __half* __restrict__ H, int i,
                                         int half, int sl, float* a) {
    #pragma unroll
    for (int k = 0; k < 8; k++) a[k] = 0.f;
    if (half == 0) addu4(ldrow(H, i, sl), a);   // self loop

    int e = i * CAP;
    const int ee = e + g_deg[i];
    for (; e + 16 <= ee; e += 16) {
        int4 c0 = *(const int4*)(g_colsrc + e);
        int4 c1 = *(const int4*)(g_colsrc + e + 4);
        int4 c2 = *(const int4*)(g_colsrc + e + 8);
        int4 c3 = *(const int4*)(g_colsrc + e + 12);
        int s0 = half ? c0.y : c0.x;
        int s1 = half ? c0.w : c0.z;
        int s2 = half ? c1.y : c1.x;
        int s3 = half ? c1.w : c1.z;
        int s4 = half ? c2.y : c2.x;
        int s5 = half ? c2.w : c2.z;
        int s6 = half ? c3.y : c3.x;
        int s7 = half ? c3.w : c3.z;
        uint4 u0 = ldrow(H, s0, sl);
        uint4 u1 = ldrow(H, s1, sl);
        uint4 u2 = ldrow(H, s2, sl);
        uint4 u3 = ldrow(H, s3, sl);
        uint4 u4 = ldrow(H, s4, sl);
        uint4 u5 = ldrow(H, s5, sl);
        uint4 u6 = ldrow(H, s6, sl);
        uint4 u7 = ldrow(H, s7, sl);
        addu4(u0, a); addu4(u1, a); addu4(u2, a); addu4(u3, a);
        addu4(u4, a); addu4(u5, a); addu4(u6, a); addu4(u7, a);
    }
    if (e + 8 <= ee) {
        int4 c0 = *(const int4*)(g_colsrc + e);
        int4 c1 = *(const int4*)(g_colsrc + e + 4);
        int s0 = half ? c0.y : c0.x;
        int s1 = half ? c0.w : c0.z;
        int s2 = half ? c1.y : c1.x;
        int s3 = half ? c1.w : c1.z;
        uint4 u0 = ldrow(H, s0, sl);
        uint4 u1 = ldrow(H, s1, sl);
        uint4 u2 = ldrow(H, s2, sl);
        uint4 u3 = ldrow(H, s3, sl);
        addu4(u0, a); addu4(u1, a); addu4(u2, a); addu4(u3, a);
        e += 8;
    }
    if (e + 4 <= ee) {
        int4 c0 = *(const int4*)(g_colsrc + e);
        int s0 = half ? c0.y : c0.x;
        int s1 = half ? c0.w : c0.z;
        uint4 u0 = ldrow(H, s0, sl);
        uint4 u1 = ldrow(H, s1, sl);
        addu4(u0, a); addu4(u1, a);
        e += 4;
    }
    if (e + 2 <= ee) {
        addu4(ldrow(H, g_colsrc[e + half], sl), a);
        e += 2;
    }
    if (e < ee && half == 0) addu4(ldrow(H, g_colsrc[e], sl), a);

    #pragma unroll
    for (int k = 0; k < 8; k++)
        a[k] += __shfl_down_sync(0xffffffffu, a[k], 16);
}

// layer-1: rows unscaled; weight each by dinv[s]
__device__ __forceinline__ void gather16_w(const __half* __restrict__ H, int i,
                                           float di, int half, int sl, float* a) {
    #pragma unroll
    for (int k = 0; k < 8; k++) a[k] = 0.f;
    if (half == 0) addu4_w(ldrow(H, i, sl), di, a);

    int e = i * CAP;
    const int ee = e + g_deg[i];
    for (; e + 16 <= ee; e += 16) {
        int4 c0 = *(const int4*)(g_colsrc + e);
        int4 c1 = *(const int4*)(g_colsrc + e + 4);
        int4 c2 = *(const int4*)(g_colsrc + e + 8);
        int4 c3 = *(const int4*)(g_colsrc + e + 12);
        int s0 = half ? c0.y : c0.x;
        int s1 = half ? c0.w : c0.z;
        int s2 = half ? c1.y : c1.x;
        int s3 = half ? c1.w : c1.z;
        int s4 = half ? c2.y : c2.x;
        int s5 = half ? c2.w : c2.z;
        int s6 = half ? c3.y : c3.x;
        int s7 = half ? c3.w : c3.z;
        float d0 = g_dinv[s0], d1 = g_dinv[s1], d2 = g_dinv[s2], d3 = g_dinv[s3];
        float d4 = g_dinv[s4], d5 = g_dinv[s5], d6 = g_dinv[s6], d7 = g_dinv[s7];
        uint4 u0 = ldrow(H, s0, sl);
        uint4 u1 = ldrow(H, s1, sl);
        uint4 u2 = ldrow(H, s2, sl);
        uint4 u3 = ldrow(H, s3, sl);
        uint4 u4 = ldrow(H, s4, sl);
        uint4 u5 = ldrow(H, s5, sl);
        uint4 u6 = ldrow(H, s6, sl);
        uint4 u7 = ldrow(H, s7, sl);
        addu4_w(u0, d0, a); addu4_w(u1, d1, a);
        addu4_w(u2, d2, a); addu4_w(u3, d3, a);
        addu4_w(u4, d4, a); addu4_w(u5, d5, a);
        addu4_w(u6, d6, a); addu4_w(u7, d7, a);
    }
    if (e + 8 <= ee) {
        int4 c0 = *(const int4*)(g_colsrc + e);
        int4 c1 = *(const int4*)(g_colsrc + e + 4);
        int s0 = half ? c0.y : c0.x;
        int s1 = half ? c0.w : c0.z;
        int s2 = half ? c1.y : c1.x;
        int s3 = half ? c1.w : c1.z;
        float d0 = g_dinv[s0], d1 = g_dinv[s1], d2 = g_dinv[s2], d3 = g_dinv[s3];
        uint4 u0 = ldrow(H, s0, sl);
        uint4 u1 = ldrow(H, s1, sl);
        uint4 u2 = ldrow(H, s2, sl);
        uint4 u3 = ldrow(H, s3, sl);
        addu4_w(u0, d0, a); addu4_w(u1, d1, a);
        addu4_w(u2, d2, a); addu4_w(u3, d3, a);
        e += 8;
    }
    if (e + 4 <= ee) {
        int4 c0 = *(const int4*)(g_colsrc + e);
        int s0 = half ? c0.y : c0.x;
        int s1 = half ? c0.w : c0.z;
        float d0 = g_dinv[s0], d1 = g_dinv[s1];
        uint4 u0 = ldrow(H, s0, sl);
        uint4 u1 = ldrow(H, s1, sl);
        addu4_w(u0, d0, a); addu4_w(u1, d1, a);
        e += 4;
    }
    if (e + 2 <= ee) {
        int s = g_colsrc[e + half];
        addu4_w(ldrow(H, s, sl), g_dinv[s], a);
        e += 2;
    }
    if (e < ee && half == 0) {
        int s = g_colsrc[e];
        addu4_w(ldrow(H, s, sl), g_dinv[s], a);
    }
    #pragma unroll
    for (int k = 0; k < 8; k++)
        a[k] += __shfl_down_sync(0xffffffffu, a[k], 16);
}

__device__ __forceinline__ void store16_relu(__half* __restrict__ O, int i, float di,
                                             const float* a, const float4 bA,
                                             const float4 bB, int sl) {
    float o[8];
    o[0] = fmaxf(a[0] * di + bA.x, 0.f);
    o[1] = fmaxf(a[1] * di + bA.y, 0.f);
    o[2] = fmaxf(a[2] * di + bA.z, 0.f);
    o[3] = fmaxf(a[3] * di + bA.w, 0.f);
    o[4] = fmaxf(a[4] * di + bB.x, 0.f);
    o[5] = fmaxf(a[5] * di + bB.y, 0.f);
    o[6] = fmaxf(a[6] * di + bB.z, 0.f);
    o[7] = fmaxf(a[7] * di + bB.w, 0.f);
    uint4 u;
    __half2 h0 = __floats2half2_rn(o[0], o[1]);
    __half2 h1 = __floats2half2_rn(o[2], o[3]);
    __half2 h2 = __floats2half2_rn(o[4], o[5]);
    __half2 h3 = __floats2half2_rn(o[6], o[7]);
    u.x = *(uint32_t*)&h0; u.y = *(uint32_t*)&h1;
    u.z = *(uint32_t*)&h2; u.w = *(uint32_t*)&h3;
    *(uint4*)(O + (size_t)i * D + sl * 8) = u;
}

#define AGRID 1184
#define NWARP (AGRID * 8)

// layer-1 aggregation (weighted), node range [n0, n1)
__global__ void k_agg1(const __half* __restrict__ H, const float* __restrict__ bias,
                       __half* __restrict__ O, int n0, int n1) {
    const int gw = (blockIdx.x * blockDim.x + threadIdx.x) >> 5;
    const int lane = threadIdx.x & 31;
    const int half = lane >> 4, sl = lane & 15;
    const float4 bA = ((const float4*)bias)[2 * sl];
    const float4 bB = ((const float4*)bias)[2 * sl + 1];

    for (int i = n0 + gw; i < n1; i += NWARP) {
        const float di = g_dinv[i];
        float a[8];
        gather16_w(H, i, di, half, sl, a);
        if (half == 0) store16_relu(O, i, di, a, bA, bB, sl);
    }
}

// layer-2 aggregation (pre-scaled rows), node range [n0, n1)
__global__ void k_agg(const __half* __restrict__ H, const float* __restrict__ bias,
                      __half* __restrict__ O, int n0, int n1) {
    const int gw = (blockIdx.x * blockDim.x + threadIdx.x) >> 5;
    const int lane = threadIdx.x & 31;
    const int half = lane >> 4, sl = lane & 15;
    const float4 bA = ((const float4*)bias)[2 * sl];
    const float4 bB = ((const float4*)bias)[2 * sl + 1];

    for (int i = n0 + gw; i < n1; i += NWARP) {
        const float di = g_dinv[i];
        float a[8];
        gather16(H, i, half, sl, a);
        if (half == 0) store16_relu(O, i, di, a, bA, bB, sl);
    }
}

// layer 3 + pool: contiguous chunks, register graph-accumulator (batch sorted)
__global__ void k_agg_pool(const __half* __restrict__ H, const float* __restrict__ bias,
                           const int* __restrict__ batch) {
    const int gw = (blockIdx.x * blockDim.x + threadIdx.x) >> 5;
    const int lane = threadIdx.x & 31;
    const int half = lane >> 4, sl = lane & 15;
    const float4 bA = ((const float4*)bias)[2 * sl];
    const float4 bB = ((const float4*)bias)[2 * sl + 1];

    const int chunk = (NN + NWARP - 1) / NWARP;     // 6
    int i0 = gw * chunk;
    if (i0 >= NN) return;
    int i1 = i0 + chunk; if (i1 > NN) i1 = NN;

    float racc[8];
    #pragma unroll
    for (int k = 0; k < 8; k++) racc[k] = 0.f;
    int gcur = batch[i0];
    int gcnt = 0;

    for (int i = i0; i < i1; i++) {
        const int g = batch[i];
        if (g != gcur) {
            if (half == 0) {
                float* dst = g_psum + gcur * D + sl * 8;
                #pragma unroll
                for (int k = 0; k < 8; k++) atomicAdd(dst + k, racc[k]);
                if (lane == 0) atomicAdd(&g_pcnt[gcur], gcnt);
            }
            #pragma unroll
            for (int k = 0; k < 8; k++) racc[k] = 0.f;
            gcur = g;
            gcnt = 0;
        }
        const float di = g_dinv[i];
        float a[8];
        gather16(H, i, half, sl, a);
        if (half == 0) {
            racc[0] += a[0] * di + bA.x;
            racc[1] += a[1] * di + bA.y;
            racc[2] += a[2] * di + bA.z;
            racc[3] += a[3] * di + bA.w;
            racc[4] += a[4] * di + bB.x;
            racc[5] += a[5] * di + bB.y;
            racc[6] += a[6] * di + bB.z;
            racc[7] += a[7] * di + bB.w;
        }
        gcnt++;
    }
    if (half == 0) {
        float* dst = g_psum + gcur * D + sl * 8;
        #pragma unroll
        for (int k = 0; k < 8; k++) atomicAdd(dst + k, racc[k]);
        if (lane == 0) atomicAdd(&g_pcnt[gcur], gcnt);
    }
}

// ---------------- head: one warp per graph ----------------
__global__ void k_final(const float* __restrict__ Wl, const float* __restrict__ bl,
                        float* __restrict__ out) {
    const int g = (blockIdx.x * blockDim.x + threadIdx.x) >> 5;
    const int lane = threadIdx.x & 31;
    if (g >= GG) return;

    const float inv = 1.0f / fmaxf((float)g_pcnt[g], 1.0f);
    float4 p4 = ((const float4*)(g_psum + g * D))[lane];
    p4.x *= inv; p4.y *= inv; p4.z *= inv; p4.w *= inv;

    const int f0 = lane * 4;
    float logits[DOUT];
    #pragma unroll
    for (int d = 0; d < DOUT; d++) {
        logits[d] = p4.x * Wl[(f0 + 0) * DOUT + d]
                  + p4.y * Wl[(f0 + 1) * DOUT + d]
                  + p4.z * Wl[(f0 + 2) * DOUT + d]
                  + p4.w * Wl[(f0 + 3) * DOUT + d];
    }
    #pragma unroll
    for (int d = 0; d < DOUT; d++) {
        #pragma unroll
        for (int off = 16; off > 0; off >>= 1)
            logits[d] += __shfl_down_sync(0xffffffffu, logits[d], off);
    }
    if (lane == 0) {
        #pragma unroll
        for (int d = 0; d < DOUT; d++) logits[d] += bl[d];
        float m = logits[0];
        #pragma unroll
        for (int d = 1; d < DOUT; d++) m = fmaxf(m, logits[d]);
        float sum = 0.f;
        #pragma unroll
        for (int d = 0; d < DOUT; d++) sum += expf(logits[d] - m);
        float lse = m + logf(sum);
        #pragma unroll
        for (int d = 0; d < DOUT; d++) out[g * DOUT + d] = logits[d] - lse;
    }
}

// ---------------- launch ----------------
// Buffer rotation: x --xconv--> h2 --gemm1--> h0 --agg1--> h1 --gemm2--> h2
//                  --agg2--> h0 --gemm3--> h1 --agg_pool/final--> out
extern "C" void kernel_launch(void* const* d_in, const int* in_sizes, int n_in,
                              void* d_out, int out_size) {
    const float* x     = (const float*)d_in[0];
    const int*   ei    = (const int*)d_in[1];
    const int*   batch = (const int*)d_in[2];
    const float* W1 = (const float*)d_in[3];
    const float* b1 = (const float*)d_in[4];
    const float* W2 = (const float*)d_in[5];
    const float* b2 = (const float*)d_in[6];
    const float* W3 = (const float*)d_in[7];
    const float* b3 = (const float*)d_in[8];
    const float* Wl = (const float*)d_in[9];
    const float* bl = (const float*)d_in[10];
    float* out = (float*)d_out;

    cudaFuncSetAttribute(k_gemm_h<false>,
                         cudaFuncAttributeMaxDynamicSharedMemorySize, (int)GEMM_SMEM);
    cudaFuncSetAttribute(k_gemm_h<true>,
                         cudaFuncAttributeMaxDynamicSharedMemorySize, (int)GEMM_SMEM);

    __half *h0, *h1, *h2;
    cudaGetSymbolAddress((void**)&h0, g_h0);
    cudaGetSymbolAddress((void**)&h1, g_h1);
    cudaGetSymbolAddress((void**)&h2, g_h2);
    void* degp;
    cudaGetSymbolAddress(&degp, g_deg);

    const int TB = 256;
    const int egrid = (EQ + TB - 1) / TB;

    cudaStream_t s2;
    cudaStreamCreate(&s2);
    cudaEvent_t evF, evB, evA1, evA1h, evG2, evB1, evB1h, evG3;
    cudaEventCreateWithFlags(&evF,   cudaEventDisableTiming);
    cudaEventCreateWithFlags(&evB,   cudaEventDisableTiming);
    cudaEventCreateWithFlags(&evA1,  cudaEventDisableTiming);
    cudaEventCreateWithFlags(&evA1h, cudaEventDisableTiming);
    cudaEventCreateWithFlags(&evG2,  cudaEventDisableTiming);
    cudaEventCreateWithFlags(&evB1,  cudaEventDisableTiming);
    cudaEventCreateWithFlags(&evB1h, cudaEventDisableTiming);
    cudaEventCreateWithFlags(&evG3,  cudaEventDisableTiming);

    cudaEventRecord(evF, 0);
    cudaStreamWaitEvent(s2, evF, 0);

    // s2: single-pass bucket CSR
    cudaMemsetAsync(degp, 0, NN * sizeof(int), s2);
    k_fill<<<egrid, TB, 0, s2>>>(ei);
    k_dinv<<<(NN + TB - 1) / TB, TB, 0, s2>>>();
    cudaEventRecord(evB, s2);

    // main: wprep + xconv + gemm1 (x fp16 in h2 -> h0; no dinv scale)
    k_wprep<<<(3 * D * D + TB - 1) / TB, TB>>>(W1, W2, W3);
    k_xconv<<<(NN * D / 4 + TB - 1) / TB, TB>>>(x);
    k_gemm_h<false><<<GGRID, TB, GEMM_SMEM>>>(h2, 0, h0, 0, NT);

    // join: aggregation needs CSR
    cudaStreamWaitEvent(0, evB, 0);

    // ---- layer 1 agg + layer 2 gemm, pipelined halves ----
    k_agg1<<<AGRID, TB>>>(h0, b1, h1, 0, NH);
    cudaEventRecord(evA1, 0);
    k_agg1<<<AGRID, TB>>>(h0, b1, h1, NH, NN);
    cudaEventRecord(evA1h, 0);

    cudaStreamWaitEvent(s2, evA1, 0);
    k_gemm_h<true><<<TH, TB, GEMM_SMEM, s2>>>(h1, 1, h2, 0, TH);
    cudaStreamWaitEvent(s2, evA1h, 0);
    k_gemm_h<true><<<NT - TH, TB, GEMM_SMEM, s2>>>(h1, 1, h2, TH, NT);
    cudaEventRecord(evG2, s2);

    // ---- layer 2 agg + layer 3 gemm, pipelined halves ----
    cudaStreamWaitEvent(0, evG2, 0);
    k_agg<<<AGRID, TB>>>(h2, b2, h0, 0, NH);
    cudaEventRecord(evB1, 0);
    k_agg<<<AGRID, TB>>>(h2, b2, h0, NH, NN);
    cudaEventRecord(evB1h, 0);

    cudaStreamWaitEvent(s2, evB1, 0);
    k_gemm_h<true><<<TH, TB, GEMM_SMEM, s2>>>(h0, 2, h1, 0, TH);
    cudaStreamWaitEvent(s2, evB1h, 0);
    k_gemm_h<true><<<NT - TH, TB, GEMM_SMEM, s2>>>(h0, 2, h1, TH, NT);
    cudaEventRecord(evG3, s2);

    // ---- layer 3 agg + pool + head ----
    cudaStreamWaitEvent(0, evG3, 0);
    k_agg_pool<<<AGRID, TB>>>(h1, b3, batch);
    k_final<<<16, TB>>>(Wl, bl, out);

    cudaEventDestroy(evF);
    cudaEventDestroy(evB);
    cudaEventDestroy(evA1);
    cudaEventDestroy(evA1h);
    cudaEventDestroy(evG2);
    cudaEventDestroy(evB1);
    cudaEventDestroy(evB1h);
    cudaEventDestroy(evG3);
    cudaStreamDestroy(s2);
}

// round 17
// speedup vs baseline: 1.1167x; 1.1167x over previous
#include <cuda_runtime.h>
#include <cuda_fp16.h>
#include <math.h>
#include <stdint.h>

#define NN   50000
#define EE   800000
#define EQ   (EE / 4)
#define D    128
#define DOUT 10
#define GG   128
#define CAP  96        // bucket capacity (P(deg>=96) ~ 1e-45 for Poisson(16))

#define NPAD (((NN + 127) / 128) * 128)
#define NT   ((NN + 127) / 128)

// ---------------- device scratch ----------------
__device__ __half g_h0[(size_t)NPAD * D];
__device__ __half g_h1[(size_t)NPAD * D];
__device__ __half g_Wt[3][D * D];
__device__ int    g_deg[NN];
__device__ float  g_dinv[NN];
__device__ int    g_colsrc[(size_t)NN * CAP];
__device__ float  g_psum[GG * D];
__device__ int    g_pcnt[GG];

// ---------------- single-pass bucket CSR ----------------
__global__ void k_fill(const int* __restrict__ ei) {
    int t = blockIdx.x * blockDim.x + threadIdx.x;
    if (t >= EQ) return;
    const int* dsts = ei + EE;
    int d0 = dsts[t];
    int d1 = dsts[t + EQ];
    int d2 = dsts[t + 2 * EQ];
    int d3 = dsts[t + 3 * EQ];
    int s0 = ei[t];
    int s1 = ei[t + EQ];
    int s2 = ei[t + 2 * EQ];
    int s3 = ei[t + 3 * EQ];
    int p0 = atomicAdd(&g_deg[d0], 1);
    int p1 = atomicAdd(&g_deg[d1], 1);
    int p2 = atomicAdd(&g_deg[d2], 1);
    int p3 = atomicAdd(&g_deg[d3], 1);
    if (p0 < CAP) g_colsrc[(size_t)d0 * CAP + p0] = s0;
    if (p1 < CAP) g_colsrc[(size_t)d1 * CAP + p1] = s1;
    if (p2 < CAP) g_colsrc[(size_t)d2 * CAP + p2] = s2;
    if (p3 < CAP) g_colsrc[(size_t)d3 * CAP + p3] = s3;
}

__global__ void k_dinv() {
    int i = blockIdx.x * blockDim.x + threadIdx.x;
    if (i < NN) g_dinv[i] = rsqrtf((float)(g_deg[i] + 1));
}

// ---------------- weight prep (+ pool buffer zeroing) ----------------
__global__ void k_wprep(const float* __restrict__ W1, const float* __restrict__ W2,
                        const float* __restrict__ W3) {
    int idx = blockIdx.x * blockDim.x + threadIdx.x;
    if (idx < GG * D) g_psum[idx] = 0.0f;
    if (idx < GG) g_pcnt[idx] = 0;
    if (idx >= 3 * D * D) return;
    int l = idx / (D * D);
    int j = idx - l * (D * D);
    int k = j >> 7, n = j & 127;
    const float* W = (l == 0) ? W1 : (l == 1) ? W2 : W3;
    g_Wt[l][n * D + k] = __float2half_rn(W[j]);
}

// ---------------- fp16 tensor-core GEMM (persistent, M=128, 2 CTA/SM) ----------
#define SMSH 136
#define GEMM_SMEM (2 * 128 * SMSH * sizeof(__half))
#define GGRID 296

#define MMA_F16(cc, a0, a1, a2, a3, b0, b1)                               \
    asm volatile("mma.sync.aligned.m16n8k16.row.col.f32.f16.f16.f32 "     \
                 "{%0,%1,%2,%3}, {%4,%5,%6,%7}, {%8,%9}, {%0,%1,%2,%3};"  \
                 : "+f"(cc[0]), "+f"(cc[1]), "+f"(cc[2]), "+f"(cc[3])     \
                 : "r"(a0), "r"(a1), "r"(a2), "r"(a3), "r"(b0), "r"(b1))

template <bool IN_HALF, bool SCALE>
__global__ void __launch_bounds__(256, 2)
k_gemm_h(const void* __restrict__ Ain, int wsel, __half* __restrict__ C) {
    cudaGridDependencySynchronize();

    extern __shared__ __half smh[];
    __half* As = smh;
    __half* Wt = smh + 128 * SMSH;
    const int t = threadIdx.x;

    {
        const uint4* src = (const uint4*)g_Wt[wsel];
        for (int j = t; j < (D * D) / 8; j += 256) {
            int n = j >> 4;
            int c8 = (j & 15) * 8;
            *(uint4*)(Wt + n * SMSH + c8) = src[j];
        }
    }

    const int w    = t >> 5;
    const int lane = t & 31;
    const int wm   = w & 3;
    const int wn   = w >> 2;
    const int quad = lane >> 2;
    const int rem  = lane & 3;
    const __half* Ab = As + (wm * 32 + quad) * SMSH + 2 * rem;
    const __half* Bb = Wt + (wn * 64 + quad) * SMSH + 2 * rem;

    for (int tile = blockIdx.x; tile < NT; tile += GGRID) {
        const int row0 = tile * 128;
        __syncthreads();

        if (IN_HALF) {
            const __half* A = (const __half*)Ain;
            for (int j = t; j < (128 * D) / 8; j += 256) {
                int r = j >> 4;
                int c8 = (j & 15) * 8;
                uint4 u = *(const uint4*)(A + (size_t)(row0 + r) * D + c8);
                *(uint4*)(As + r * SMSH + c8) = u;
            }
        } else {
            const float* A = (const float*)Ain;
            for (int j = t; j < (128 * D) / 4; j += 256) {
                int r = j >> 5;
                int c4 = (j & 31) * 4;
                float4 v = make_float4(0.f, 0.f, 0.f, 0.f);
                if (row0 + r < NN)
                    v = *(const float4*)(A + (size_t)(row0 + r) * D + c4);
                __half2 h01 = __floats2half2_rn(v.x, v.y);
                __half2 h23 = __floats2half2_rn(v.z, v.w);
                uint2 u;
                u.x = *(uint32_t*)&h01;
                u.y = *(uint32_t*)&h23;
                *(uint2*)(As + r * SMSH + c4) = u;
            }
        }
        __syncthreads();

        float acc[2][8][4];
        #pragma unroll
        for (int m = 0; m < 2; m++)
            #pragma unroll
            for (int j = 0; j < 8; j++)
                #pragma unroll
                for (int r = 0; r < 4; r++) acc[m][j][r] = 0.f;

        #pragma unroll
        for (int ks = 0; ks < 8; ks++) {
            const int k0 = ks * 16;
            uint32_t a[2][4];
            #pragma unroll
            for (int m = 0; m < 2; m++) {
                const __half* p = Ab + m * 16 * SMSH + k0;
                a[m][0] = *(const uint32_t*)(p);
                a[m][1] = *(const uint32_t*)(p + 8 * SMSH);
                a[m][2] = *(const uint32_t*)(p + 8);
                a[m][3] = *(const uint32_t*)(p + 8 * SMSH + 8);
            }
            #pragma unroll
            for (int j = 0; j < 8; j++) {
                const __half* q = Bb + j * 8 * SMSH + k0;
                uint32_t b0 = *(const uint32_t*)(q);
                uint32_t b1 = *(const uint32_t*)(q + 8);
                MMA_F16(acc[0][j], a[0][0], a[0][1], a[0][2], a[0][3], b0, b1);
                MMA_F16(acc[1][j], a[1][0], a[1][1], a[1][2], a[1][3], b0, b1);
            }
        }

        #pragma unroll
        for (int m = 0; m < 2; m++) {
            int r = row0 + wm * 32 + m * 16 + quad;
            float di0 = 1.f, di1 = 1.f;
            if (SCALE) {
                di0 = (r < NN)     ? g_dinv[r]     : 0.f;
                di1 = (r + 8 < NN) ? g_dinv[r + 8] : 0.f;
            }
            #pragma unroll
            for (int j = 0; j < 8; j++) {
                int cb = wn * 64 + j * 8 + rem * 2;
                if (r < NN) {
                    __half2 h = __floats2half2_rn(acc[m][j][0] * di0, acc[m][j][1] * di0);
                    *(uint32_t*)(C + (size_t)r * D + cb) = *(uint32_t*)&h;
                }
                if (r + 8 < NN) {
                    __half2 h = __floats2half2_rn(acc[m][j][2] * di1, acc[m][j][3] * di1);
                    *(uint32_t*)(C + (size_t)(r + 8) * D + cb) = *(uint32_t*)&h;
                }
            }
        }
    }
}

// ---------------- 16-lane-per-row aggregation, MLP-8 + int4 index loads ------
__device__ __forceinline__ void addu4(const uint4& u, float* a) {
    const __half2* h = (const __half2*)&u;
    #pragma unroll
    for (int q = 0; q < 4; q++) {
        float2 f = __half22float2(h[q]);
        a[2 * q + 0] += f.x;
        a[2 * q + 1] += f.y;
    }
}

__device__ __forceinline__ void addu4_w(const uint4& u, float ds, float* a) {
    const __half2* h = (const __half2*)&u;
    #pragma unroll
    for (int q = 0; q < 4; q++) {
        float2 f = __half22float2(h[q]);
        a[2 * q + 0] += f.x * ds;
        a[2 * q + 1] += f.y * ds;
    }
}

__device__ __forceinline__ uint4 ldrow(const __half* __restrict__ H, int s, int sl) {
    return *(const uint4*)(H + (size_t)s * D + sl * 8);
}

// rows pre-scaled by dinv[s] (layers 2,3)
__device__ __forceinline__ void gather16(const __half* __restrict__ H, int i,
                                         int half, int sl, float* a) {
    #pragma unroll
    for (int k = 0; k < 8; k++) a[k] = 0.f;
    if (half == 0) addu4(ldrow(H, i, sl), a);   // self loop

    int e = i * CAP;
    const int ee = e + g_deg[i];
    for (; e + 16 <= ee; e += 16) {
        int4 c0 = *(const int4*)(g_colsrc + e);
        int4 c1 = *(const int4*)(g_colsrc + e + 4);
        int4 c2 = *(const int4*)(g_colsrc + e + 8);
        int4 c3 = *(const int4*)(g_colsrc + e + 12);
        int s0 = half ? c0.y : c0.x;
        int s1 = half ? c0.w : c0.z;
        int s2 = half ? c1.y : c1.x;
        int s3 = half ? c1.w : c1.z;
        int s4 = half ? c2.y : c2.x;
        int s5 = half ? c2.w : c2.z;
        int s6 = half ? c3.y : c3.x;
        int s7 = half ? c3.w : c3.z;
        uint4 u0 = ldrow(H, s0, sl);
        uint4 u1 = ldrow(H, s1, sl);
        uint4 u2 = ldrow(H, s2, sl);
        uint4 u3 = ldrow(H, s3, sl);
        uint4 u4 = ldrow(H, s4, sl);
        uint4 u5 = ldrow(H, s5, sl);
        uint4 u6 = ldrow(H, s6, sl);
        uint4 u7 = ldrow(H, s7, sl);
        addu4(u0, a); addu4(u1, a); addu4(u2, a); addu4(u3, a);
        addu4(u4, a); addu4(u5, a); addu4(u6, a); addu4(u7, a);
    }
    if (e + 8 <= ee) {
        int4 c0 = *(const int4*)(g_colsrc + e);
        int4 c1 = *(const int4*)(g_colsrc + e + 4);
        int s0 = half ? c0.y : c0.x;
        int s1 = half ? c0.w : c0.z;
        int s2 = half ? c1.y : c1.x;
        int s3 = half ? c1.w : c1.z;
        uint4 u0 = ldrow(H, s0, sl);
        uint4 u1 = ldrow(H, s1, sl);
        uint4 u2 = ldrow(H, s2, sl);
        uint4 u3 = ldrow(H, s3, sl);
        addu4(u0, a); addu4(u1, a); addu4(u2, a); addu4(u3, a);
        e += 8;
    }
    if (e + 4 <= ee) {
        int4 c0 = *(const int4*)(g_colsrc + e);
        int s0 = half ? c0.y : c0.x;
        int s1 = half ? c0.w : c0.z;
        uint4 u0 = ldrow(H, s0, sl);
        uint4 u1 = ldrow(H, s1, sl);
        addu4(u0, a); addu4(u1, a);
        e += 4;
    }
    if (e + 2 <= ee) {
        addu4(ldrow(H, g_colsrc[e + half], sl), a);
        e += 2;
    }
    if (e < ee && half == 0) addu4(ldrow(H, g_colsrc[e], sl), a);

    #pragma unroll
    for (int k = 0; k < 8; k++)
        a[k] += __shfl_down_sync(0xffffffffu, a[k], 16);
}

// layer-1: rows unscaled; weight each by dinv[s]
__device__ __forceinline__ void gather16_w(const __half* __restrict__ H, int i,
                                           float di, int half, int sl, float* a) {
    #pragma unroll
    for (int k = 0; k < 8; k++) a[k] = 0.f;
    if (half == 0) addu4_w(ldrow(H, i, sl), di, a);

    int e = i * CAP;
    const int ee = e + g_deg[i];
    for (; e + 16 <= ee; e += 16) {
        int4 c0 = *(const int4*)(g_colsrc + e);
        int4 c1 = *(const int4*)(g_colsrc + e + 4);
        int4 c2 = *(const int4*)(g_colsrc + e + 8);
        int4 c3 = *(const int4*)(g_colsrc + e + 12);
        int s0 = half ? c0.y : c0.x;
        int s1 = half ? c0.w : c0.z;
        int s2 = half ? c1.y : c1.x;
        int s3 = half ? c1.w : c1.z;
        int s4 = half ? c2.y : c2.x;
        int s5 = half ? c2.w : c2.z;
        int s6 = half ? c3.y : c3.x;
        int s7 = half ? c3.w : c3.z;
        float d0 = g_dinv[s0], d1 = g_dinv[s1], d2 = g_dinv[s2], d3 = g_dinv[s3];
        float d4 = g_dinv[s4], d5 = g_dinv[s5], d6 = g_dinv[s6], d7 = g_dinv[s7];
        uint4 u0 = ldrow(H, s0, sl);
        uint4 u1 = ldrow(H, s1, sl);
        uint4 u2 = ldrow(H, s2, sl);
        uint4 u3 = ldrow(H, s3, sl);
        uint4 u4 = ldrow(H, s4, sl);
        uint4 u5 = ldrow(H, s5, sl);
        uint4 u6 = ldrow(H, s6, sl);
        uint4 u7 = ldrow(H, s7, sl);
        addu4_w(u0, d0, a); addu4_w(u1, d1, a);
        addu4_w(u2, d2, a); addu4_w(u3, d3, a);
        addu4_w(u4, d4, a); addu4_w(u5, d5, a);
        addu4_w(u6, d6, a); addu4_w(u7, d7, a);
    }
    if (e + 8 <= ee) {
        int4 c0 = *(const int4*)(g_colsrc + e);
        int4 c1 = *(const int4*)(g_colsrc + e + 4);
        int s0 = half ? c0.y : c0.x;
        int s1 = half ? c0.w : c0.z;
        int s2 = half ? c1.y : c1.x;
        int s3 = half ? c1.w : c1.z;
        float d0 = g_dinv[s0], d1 = g_dinv[s1], d2 = g_dinv[s2], d3 = g_dinv[s3];
        uint4 u0 = ldrow(H, s0, sl);
        uint4 u1 = ldrow(H, s1, sl);
        uint4 u2 = ldrow(H, s2, sl);
        uint4 u3 = ldrow(H, s3, sl);
        addu4_w(u0, d0, a); addu4_w(u1, d1, a);
        addu4_w(u2, d2, a); addu4_w(u3, d3, a);
        e += 8;
    }
    if (e + 4 <= ee) {
        int4 c0 = *(const int4*)(g_colsrc + e);
        int s0 = half ? c0.y : c0.x;
        int s1 = half ? c0.w : c0.z;
        float d0 = g_dinv[s0], d1 = g_dinv[s1];
        uint4 u0 = ldrow(H, s0, sl);
        uint4 u1 = ldrow(H, s1, sl);
        addu4_w(u0, d0, a); addu4_w(u1, d1, a);
        e += 4;
    }
    if (e + 2 <= ee) {
        int s = g_colsrc[e + half];
        addu4_w(ldrow(H, s, sl), g_dinv[s], a);
        e += 2;
    }
    if (e < ee && half == 0) {
        int s = g_colsrc[e];
        addu4_w(ldrow(H, s, sl), g_dinv[s], a);
    }
    #pragma unroll
    for (int k = 0; k < 8; k++)
        a[k] += __shfl_down_sync(0xffffffffu, a[k], 16);
}

__device__ __forceinline__ void store16_relu(__half* __restrict__ O, int i, float di,
                                             const float* a, const float4 bA,
                                             const float4 bB, int sl) {
    float o[8];
    o[0] = fmaxf(a[0] * di + bA.x, 0.f);
    o[1] = fmaxf(a[1] * di + bA.y, 0.f);
    o[2] = fmaxf(a[2] * di + bA.z, 0.f);
    o[3] = fmaxf(a[3] * di + bA.w, 0.f);
    o[4] = fmaxf(a[4] * di + bB.x, 0.f);
    o[5] = fmaxf(a[5] * di + bB.y, 0.f);
    o[6] = fmaxf(a[6] * di + bB.z, 0.f);
    o[7] = fmaxf(a[7] * di + bB.w, 0.f);
    uint4 u;
    __half2 h0 = __floats2half2_rn(o[0], o[1]);
    __half2 h1 = __floats2half2_rn(o[2], o[3]);
    __half2 h2 = __floats2half2_rn(o[4], o[5]);
    __half2 h3 = __floats2half2_rn(o[6], o[7]);
    u.x = *(uint32_t*)&h0; u.y = *(uint32_t*)&h1;
    u.z = *(uint32_t*)&h2; u.w = *(uint32_t*)&h3;
    *(uint4*)(O + (size_t)i * D + sl * 8) = u;
}

#define AGRID 1184
#define NWARP (AGRID * 8)

__global__ void k_agg1(const __half* __restrict__ H, const float* __restrict__ bias,
                       __half* __restrict__ O) {
    const int gw = (blockIdx.x * blockDim.x + threadIdx.x) >> 5;
    const int lane = threadIdx.x & 31;
    const int half = lane >> 4, sl = lane & 15;
    const float4 bA = ((const float4*)bias)[2 * sl];
    const float4 bB = ((const float4*)bias)[2 * sl + 1];
    cudaGridDependencySynchronize();

    for (int i = gw; i < NN; i += NWARP) {
        const float di = g_dinv[i];
        float a[8];
        gather16_w(H, i, di, half, sl, a);
        if (half == 0) store16_relu(O, i, di, a, bA, bB, sl);
    }
}

__global__ void k_agg(const __half* __restrict__ H, const float* __restrict__ bias,
                      __half* __restrict__ O) {
    const int gw = (blockIdx.x * blockDim.x + threadIdx.x) >> 5;
    const int lane = threadIdx.x & 31;
    const int half = lane >> 4, sl = lane & 15;
    const float4 bA = ((const float4*)bias)[2 * sl];
    const float4 bB = ((const float4*)bias)[2 * sl + 1];
    cudaGridDependencySynchronize();

    for (int i = gw; i < NN; i += NWARP) {
        const float di = g_dinv[i];
        float a[8];
        gather16(H, i, half, sl, a);
        if (half == 0) store16_relu(O, i, di, a, bA, bB, sl);
    }
}

// layer 3 + pool: contiguous chunks, register graph-accumulator (batch sorted)
__global__ void k_agg_pool(const __half* __restrict__ H, const float* __restrict__ bias,
                           const int* __restrict__ batch) {
    const int gw = (blockIdx.x * blockDim.x + threadIdx.x) >> 5;
    const int lane = threadIdx.x & 31;
    const int half = lane >> 4, sl = lane & 15;
    const float4 bA = ((const float4*)bias)[2 * sl];
    const float4 bB = ((const float4*)bias)[2 * sl + 1];
    cudaGridDependencySynchronize();

    const int chunk = (NN + NWARP - 1) / NWARP;     // 6
    int i0 = gw * chunk;
    if (i0 >= NN) return;
    int i1 = i0 + chunk; if (i1 > NN) i1 = NN;

    float racc[8];
    #pragma unroll
    for (int k = 0; k < 8; k++) racc[k] = 0.f;
    int gcur = batch[i0];
    int gcnt = 0;

    for (int i = i0; i < i1; i++) {
        const int g = batch[i];
        if (g != gcur) {
            if (half == 0) {
                float* dst = g_psum + gcur * D + sl * 8;
                #pragma unroll
                for (int k = 0; k < 8; k++) atomicAdd(dst + k, racc[k]);
                if (lane == 0) atomicAdd(&g_pcnt[gcur], gcnt);
            }
            #pragma unroll
            for (int k = 0; k < 8; k++) racc[k] = 0.f;
            gcur = g;
            gcnt = 0;
        }
        const float di = g_dinv[i];
        float a[8];
        gather16(H, i, half, sl, a);
        if (half == 0) {
            racc[0] += a[0] * di + bA.x;
            racc[1] += a[1] * di + bA.y;
            racc[2] += a[2] * di + bA.z;
            racc[3] += a[3] * di + bA.w;
            racc[4] += a[4] * di + bB.x;
            racc[5] += a[5] * di + bB.y;
            racc[6] += a[6] * di + bB.z;
            racc[7] += a[7] * di + bB.w;
        }
        gcnt++;
    }
    if (half == 0) {
        float* dst = g_psum + gcur * D + sl * 8;
        #pragma unroll
        for (int k = 0; k < 8; k++) atomicAdd(dst + k, racc[k]);
        if (lane == 0) atomicAdd(&g_pcnt[gcur], gcnt);
    }
}

// ---------------- head: one warp per graph ----------------
__global__ void k_final(const float* __restrict__ Wl, const float* __restrict__ bl,
                        float* __restrict__ out) {
    const int g = (blockIdx.x * blockDim.x + threadIdx.x) >> 5;
    const int lane = threadIdx.x & 31;
    cudaGridDependencySynchronize();
    if (g >= GG) return;

    const float inv = 1.0f / fmaxf((float)g_pcnt[g], 1.0f);
    float4 p4 = ((const float4*)(g_psum + g * D))[lane];
    p4.x *= inv; p4.y *= inv; p4.z *= inv; p4.w *= inv;

    const int f0 = lane * 4;
    float logits[DOUT];
    #pragma unroll
    for (int d = 0; d < DOUT; d++) {
        logits[d] = p4.x * Wl[(f0 + 0) * DOUT + d]
                  + p4.y * Wl[(f0 + 1) * DOUT + d]
                  + p4.z * Wl[(f0 + 2) * DOUT + d]
                  + p4.w * Wl[(f0 + 3) * DOUT + d];
    }
    #pragma unroll
    for (int d = 0; d < DOUT; d++) {
        #pragma unroll
        for (int off = 16; off > 0; off >>= 1)
            logits[d] += __shfl_down_sync(0xffffffffu, logits[d], off);
    }
    if (lane == 0) {
        #pragma unroll
        for (int d = 0; d < DOUT; d++) logits[d] += bl[d];
        float m = logits[0];
        #pragma unroll
        for (int d = 1; d < DOUT; d++) m = fmaxf(m, logits[d]);
        float sum = 0.f;
        #pragma unroll
        for (int d = 0; d < DOUT; d++) sum += expf(logits[d] - m);
        float lse = m + logf(sum);
        #pragma unroll
        for (int d = 0; d < DOUT; d++) out[g * DOUT + d] = logits[d] - lse;
    }
}

// ---------------- launch ----------------
extern "C" void kernel_launch(void* const* d_in, const int* in_sizes, int n_in,
                              void* d_out, int out_size) {
    const float* x     = (const float*)d_in[0];
    const int*   ei    = (const int*)d_in[1];
    const int*   batch = (const int*)d_in[2];
    const float* W1 = (const float*)d_in[3];
    const float* b1 = (const float*)d_in[4];
    const float* W2 = (const float*)d_in[5];
    const float* b2 = (const float*)d_in[6];
    const float* W3 = (const float*)d_in[7];
    const float* b3 = (const float*)d_in[8];
    const float* Wl = (const float*)d_in[9];
    const float* bl = (const float*)d_in[10];
    float* out = (float*)d_out;

    cudaFuncSetAttribute(k_gemm_h<false, false>,
                         cudaFuncAttributeMaxDynamicSharedMemorySize, (int)GEMM_SMEM);
    cudaFuncSetAttribute(k_gemm_h<true, true>,
                         cudaFuncAttributeMaxDynamicSharedMemorySize, (int)GEMM_SMEM);

    __half *h0, *h1;
    cudaGetSymbolAddress((void**)&h0, g_h0);
    cudaGetSymbolAddress((void**)&h1, g_h1);
    void* degp;
    cudaGetSymbolAddress(&degp, g_deg);

    const int TB = 256;
    const int egrid = (EQ + TB - 1) / TB;

    cudaStream_t s2;
    cudaStreamCreate(&s2);
    cudaEvent_t evF, evB;
    cudaEventCreateWithFlags(&evF, cudaEventDisableTiming);
    cudaEventCreateWithFlags(&evB, cudaEventDisableTiming);

    cudaEventRecord(evF, 0);
    cudaStreamWaitEvent(s2, evF, 0);

    // s2: single-pass bucket CSR (memset -> fill -> dinv)
    cudaMemsetAsync(degp, 0, NN * sizeof(int), s2);
    k_fill<<<egrid, TB, 0, s2>>>(ei);
    k_dinv<<<(NN + TB - 1) / TB, TB, 0, s2>>>();
    cudaEventRecord(evB, s2);

    // main: wprep + gemm1 (overlaps CSR arm)
    k_wprep<<<(3 * D * D + TB - 1) / TB, TB>>>(W1, W2, W3);
    k_gemm_h<false, false><<<GGRID, TB, GEMM_SMEM>>>(x, 0, h0);

    // join: post-join chain with PDL
    cudaStreamWaitEvent(0, evB, 0);

    cudaLaunchAttribute pdl[1];
    pdl[0].id = cudaLaunchAttributeProgrammaticStreamSerialization;
    pdl[0].val.programmaticStreamSerializationAllowed = 1;

    cudaLaunchConfig_t cfgA = {};
    cfgA.gridDim = dim3(AGRID); cfgA.blockDim = dim3(TB);
    cfgA.stream = 0; cfgA.attrs = pdl; cfgA.numAttrs = 1;

    cudaLaunchConfig_t cfgG = {};
    cfgG.gridDim = dim3(GGRID); cfgG.blockDim = dim3(TB);
    cfgG.dynamicSmemBytes = GEMM_SMEM;
    cfgG.stream = 0; cfgG.attrs = pdl; cfgG.numAttrs = 1;

    cudaLaunchConfig_t cfgF = {};
    cfgF.gridDim = dim3(16); cfgF.blockDim = dim3(TB);
    cfgF.stream = 0; cfgF.attrs = pdl; cfgF.numAttrs = 1;

    cudaLaunchKernelEx(&cfgA, k_agg1, (const __half*)h0, b1, (__half*)h1);
    cudaLaunchKernelEx(&cfgG, k_gemm_h<true, true>, (const void*)h1, 1, (__half*)h0);
    cudaLaunchKernelEx(&cfgA, k_agg, (const __half*)h0, b2, (__half*)h1);
    cudaLaunchKernelEx(&cfgG, k_gemm_h<true, true>, (const void*)h1, 2, (__half*)h0);
    cudaLaunchKernelEx(&cfgA, k_agg_pool, (const __half*)h0, b3, batch);
    cudaLaunchKernelEx(&cfgF, k_final, Wl, bl, out);

    cudaEventDestroy(evF);
    cudaEventDestroy(evB);
    cudaStreamDestroy(s2);
}